// round 1
// baseline (speedup 1.0000x reference)
#include <cuda_runtime.h>
#include <math.h>

// ---------------- problem constants ----------------
#define S_LEN 2048
#define HID   4096
#define NH    32
#define NKV   8
#define HD    128
#define QS    (NH * HD)          // 4096
#define KVS   (NKV * HD)         // 1024
#define QKV_N (QS + 2 * KVS)     // 6144
#define SCALE 0.08838834764831845f  // 128^-0.5

// ---------------- scratch (static device globals; no allocs) ----------------
__device__ float g_qkv[S_LEN * QKV_N];       // QKV projection output [S, 6144]
__device__ float g_q[NH * S_LEN * HD];       // RoPE'd Q, head-major [h][s][d]
__device__ float g_k[NKV * S_LEN * HD];      // RoPE'd K, head-major
__device__ float g_v[NKV * S_LEN * HD];      // V, head-major
__device__ float g_attn[S_LEN * QS];         // attention output [s][h*128+d]

// ==========================================================================
// SGEMM: C[M,N] = A[M,K] @ B[K,N], row-major, all dims multiples of 128/8.
// 128x128 block tile, BK=8, 256 threads, 8x8 per-thread microtile.
// ==========================================================================
__global__ __launch_bounds__(256) void sgemm128(
    const float* __restrict__ A, const float* __restrict__ B,
    float* __restrict__ C, int M, int N, int K)
{
    __shared__ float As[8][128];   // A tile transposed: As[k][m]
    __shared__ float Bs[8][128];   // B tile: Bs[k][n]

    const int tid  = threadIdx.x;
    const int brow = blockIdx.y * 128;
    const int bcol = blockIdx.x * 128;

    const int aRow = tid >> 1;          // 0..127
    const int aCol = (tid & 1) * 4;     // 0 or 4
    const int bRow = tid >> 5;          // 0..7
    const int bCol = (tid & 31) * 4;    // 0..124

    const int ty = tid >> 4;            // 0..15
    const int tx = tid & 15;            // 0..15

    float acc[8][8];
#pragma unroll
    for (int i = 0; i < 8; i++)
#pragma unroll
        for (int j = 0; j < 8; j++) acc[i][j] = 0.0f;

    const float* Aptr = A + (size_t)(brow + aRow) * K + aCol;
    const float* Bptr = B + (size_t)bRow * N + bcol + bCol;

    for (int k0 = 0; k0 < K; k0 += 8) {
        float4 av = *(const float4*)(Aptr + k0);
        As[aCol + 0][aRow] = av.x;
        As[aCol + 1][aRow] = av.y;
        As[aCol + 2][aRow] = av.z;
        As[aCol + 3][aRow] = av.w;
        *(float4*)&Bs[bRow][bCol] = *(const float4*)(Bptr + (size_t)k0 * N);
        __syncthreads();

#pragma unroll
        for (int kk = 0; kk < 8; kk++) {
            float ar[8], br[8];
            *(float4*)(ar)     = *(float4*)&As[kk][ty * 8];
            *(float4*)(ar + 4) = *(float4*)&As[kk][ty * 8 + 4];
            *(float4*)(br)     = *(float4*)&Bs[kk][tx * 8];
            *(float4*)(br + 4) = *(float4*)&Bs[kk][tx * 8 + 4];
#pragma unroll
            for (int i = 0; i < 8; i++)
#pragma unroll
                for (int j = 0; j < 8; j++)
                    acc[i][j] = fmaf(ar[i], br[j], acc[i][j]);
        }
        __syncthreads();
    }

#pragma unroll
    for (int i = 0; i < 8; i++) {
        float* crow = C + (size_t)(brow + ty * 8 + i) * N + bcol + tx * 8;
        *(float4*)(crow)     = make_float4(acc[i][0], acc[i][1], acc[i][2], acc[i][3]);
        *(float4*)(crow + 4) = make_float4(acc[i][4], acc[i][5], acc[i][6], acc[i][7]);
    }
}

// ==========================================================================
// RoPE + split: g_qkv[s] -> g_q / g_k (NeoX rope) / g_v (copy), head-major.
// one block per token.
// ==========================================================================
__global__ __launch_bounds__(256) void rope_split_kernel(const int* __restrict__ positions)
{
    const int s   = blockIdx.x;
    const int tid = threadIdx.x;
    __shared__ float cs[64], sn[64];

    if (tid < 64) {
        float inv_freq = powf(10000.0f, -((float)(2 * tid)) / 128.0f);
        float ang = (float)positions[s] * inv_freq;
        cs[tid] = cosf(ang);
        sn[tid] = sinf(ang);
    }
    __syncthreads();

    const float* row = g_qkv + (size_t)s * QKV_N;

    // Q heads: 32 heads x 64 rotation pairs
    for (int idx = tid; idx < NH * 64; idx += 256) {
        int h = idx >> 6, d = idx & 63;
        float x1 = row[h * HD + d];
        float x2 = row[h * HD + d + 64];
        float* q = g_q + ((size_t)h * S_LEN + s) * HD;
        q[d]      = x1 * cs[d] - x2 * sn[d];
        q[d + 64] = x2 * cs[d] + x1 * sn[d];
    }
    // K heads
    for (int idx = tid; idx < NKV * 64; idx += 256) {
        int h = idx >> 6, d = idx & 63;
        const float* kr = row + QS;
        float x1 = kr[h * HD + d];
        float x2 = kr[h * HD + d + 64];
        float* k = g_k + ((size_t)h * S_LEN + s) * HD;
        k[d]      = x1 * cs[d] - x2 * sn[d];
        k[d + 64] = x2 * cs[d] + x1 * sn[d];
    }
    // V copy
    for (int idx = tid; idx < NKV * HD; idx += 256) {
        int h = idx >> 7, d = idx & 127;
        g_v[((size_t)h * S_LEN + s) * HD + d] = row[QS + KVS + h * HD + d];
    }
}

// ==========================================================================
// Flash attention, fp32, causal. Br=Bc=64, 256 threads.
// grid = (S/64 q-tiles, 32 heads). Output -> g_attn[s][h*128+d].
// ==========================================================================
#define BR 64
#define BC 64
#define QK_STRIDE (BR + 4)    // 68 (also used for Kst, Ps)
#define V_STRIDE  (HD + 4)    // 132
#define FLASH_SMEM_FLOATS (HD * QK_STRIDE /*Qst*/ + HD * QK_STRIDE /*Kst*/ \
                         + BC * V_STRIDE /*Vs*/ + BR * QK_STRIDE /*Ps*/)

__global__ __launch_bounds__(256) void flash_attn_kernel()
{
    extern __shared__ float smem[];
    float* Qst = smem;                        // [HD][68]  (transposed: [d][r])
    float* Kst = Qst + HD * QK_STRIDE;        // [HD][68]  ([d][c])
    float* Vs  = Kst + HD * QK_STRIDE;        // [BC][132] ([c][d])
    float* Ps  = Vs  + BC * V_STRIDE;         // [BR][68]  ([r][c])

    const int qt  = blockIdx.x;         // q tile 0..31
    const int h   = blockIdx.y;         // head 0..31
    const int kvh = h >> 2;             // GQA: 4 q heads per kv head
    const int tid = threadIdx.x;
    const int ty  = tid >> 4;           // 0..15 (row group)
    const int tx  = tid & 15;           // 0..15 (col group)
    const int qbase = qt * BR;

    // --- load Q tile transposed (conflict-free stores: consecutive lanes -> consecutive r/c)
    {
        const float* Qg = g_q + ((size_t)h * S_LEN + qbase) * HD;
        int r = tid & 63;
        int d0 = (tid >> 6) << 2;
#pragma unroll
        for (int i = 0; i < 8; i++) {
            int d = d0 + i * 16;
            float4 v = *(const float4*)(Qg + r * HD + d);
            Qst[(d + 0) * QK_STRIDE + r] = v.x;
            Qst[(d + 1) * QK_STRIDE + r] = v.y;
            Qst[(d + 2) * QK_STRIDE + r] = v.z;
            Qst[(d + 3) * QK_STRIDE + r] = v.w;
        }
    }

    float Ofrag[4][8];
    float m_i[4], l_i[4];
#pragma unroll
    for (int i = 0; i < 4; i++) {
        m_i[i] = -1e30f;
        l_i[i] = 0.0f;
#pragma unroll
        for (int j = 0; j < 8; j++) Ofrag[i][j] = 0.0f;
    }

    for (int jt = 0; jt <= qt; jt++) {
        const int kbase = jt * BC;
        // --- load K (transposed) and V tiles
        {
            const float* Kg = g_k + ((size_t)kvh * S_LEN + kbase) * HD;
            const float* Vg = g_v + ((size_t)kvh * S_LEN + kbase) * HD;
            int c = tid & 63;
            int d0 = (tid >> 6) << 2;
#pragma unroll
            for (int i = 0; i < 8; i++) {
                int d = d0 + i * 16;
                float4 kv = *(const float4*)(Kg + c * HD + d);
                Kst[(d + 0) * QK_STRIDE + c] = kv.x;
                Kst[(d + 1) * QK_STRIDE + c] = kv.y;
                Kst[(d + 2) * QK_STRIDE + c] = kv.z;
                Kst[(d + 3) * QK_STRIDE + c] = kv.w;
                float4 vv = *(const float4*)(Vg + c * HD + d);
                *(float4*)&Vs[c * V_STRIDE + d] = vv;
            }
        }
        __syncthreads();

        // --- S = Q @ K^T (4x4 fragment per thread)
        float sfrag[4][4];
#pragma unroll
        for (int i = 0; i < 4; i++)
#pragma unroll
            for (int j = 0; j < 4; j++) sfrag[i][j] = 0.0f;

#pragma unroll 4
        for (int kk = 0; kk < HD; kk++) {
            float4 a = *(float4*)&Qst[kk * QK_STRIDE + ty * 4];
            float4 b = *(float4*)&Kst[kk * QK_STRIDE + tx * 4];
            float ar[4] = {a.x, a.y, a.z, a.w};
            float br[4] = {b.x, b.y, b.z, b.w};
#pragma unroll
            for (int i = 0; i < 4; i++)
#pragma unroll
                for (int j = 0; j < 4; j++)
                    sfrag[i][j] = fmaf(ar[i], br[j], sfrag[i][j]);
        }

        // --- scale + causal mask (only on the diagonal tile)
        if (jt == qt) {
#pragma unroll
            for (int i = 0; i < 4; i++)
#pragma unroll
                for (int j = 0; j < 4; j++) {
                    float sv = sfrag[i][j] * SCALE;
                    sfrag[i][j] = (tx * 4 + j > ty * 4 + i) ? -1e30f : sv;
                }
        } else {
#pragma unroll
            for (int i = 0; i < 4; i++)
#pragma unroll
                for (int j = 0; j < 4; j++) sfrag[i][j] *= SCALE;
        }

        // --- online softmax (rows reduced across the 16 tx lanes; width-16 shuffles
        //     align with ty groups since tid = ty*16 + tx)
#pragma unroll
        for (int i = 0; i < 4; i++) {
            float mloc = fmaxf(fmaxf(sfrag[i][0], sfrag[i][1]),
                               fmaxf(sfrag[i][2], sfrag[i][3]));
#pragma unroll
            for (int off = 8; off > 0; off >>= 1)
                mloc = fmaxf(mloc, __shfl_xor_sync(0xffffffffu, mloc, off, 16));

            float mnew  = fmaxf(m_i[i], mloc);
            float alpha = __expf(m_i[i] - mnew);
            float rsum = 0.0f;
            float p[4];
#pragma unroll
            for (int j = 0; j < 4; j++) {
                p[j] = __expf(sfrag[i][j] - mnew);
                rsum += p[j];
            }
            *(float4*)&Ps[(ty * 4 + i) * QK_STRIDE + tx * 4] =
                make_float4(p[0], p[1], p[2], p[3]);
#pragma unroll
            for (int off = 8; off > 0; off >>= 1)
                rsum += __shfl_xor_sync(0xffffffffu, rsum, off, 16);

            l_i[i] = l_i[i] * alpha + rsum;
            m_i[i] = mnew;
#pragma unroll
            for (int j = 0; j < 8; j++) Ofrag[i][j] *= alpha;
        }
        __syncthreads();

        // --- O += P @ V (thread owns rows ty*4..+3, cols tx*8..+7)
#pragma unroll 4
        for (int c = 0; c < BC; c++) {
            float4 v0 = *(float4*)&Vs[c * V_STRIDE + tx * 8];
            float4 v1 = *(float4*)&Vs[c * V_STRIDE + tx * 8 + 4];
            float vv[8] = {v0.x, v0.y, v0.z, v0.w, v1.x, v1.y, v1.z, v1.w};
#pragma unroll
            for (int i = 0; i < 4; i++) {
                float pv = Ps[(ty * 4 + i) * QK_STRIDE + c];
#pragma unroll
                for (int j = 0; j < 8; j++)
                    Ofrag[i][j] = fmaf(pv, vv[j], Ofrag[i][j]);
            }
        }
        __syncthreads();
    }

    // --- epilogue: normalize and write to g_attn[s][h*128+d]
#pragma unroll
    for (int i = 0; i < 4; i++) {
        float inv_l = 1.0f / l_i[i];
        float* orow = g_attn + (size_t)(qbase + ty * 4 + i) * QS + h * HD + tx * 8;
        *(float4*)(orow) = make_float4(Ofrag[i][0] * inv_l, Ofrag[i][1] * inv_l,
                                       Ofrag[i][2] * inv_l, Ofrag[i][3] * inv_l);
        *(float4*)(orow + 4) = make_float4(Ofrag[i][4] * inv_l, Ofrag[i][5] * inv_l,
                                           Ofrag[i][6] * inv_l, Ofrag[i][7] * inv_l);
    }
}

// ==========================================================================
// launch
// ==========================================================================
extern "C" void kernel_launch(void* const* d_in, const int* in_sizes, int n_in,
                              void* d_out, int out_size)
{
    const int*   positions = (const int*)d_in[0];
    const float* hidden    = (const float*)d_in[1];
    const float* w_qkv     = (const float*)d_in[2];
    const float* w_o       = (const float*)d_in[3];
    float*       out       = (float*)d_out;

    void *p_qkv, *p_attn;
    cudaGetSymbolAddress(&p_qkv,  g_qkv);
    cudaGetSymbolAddress(&p_attn, g_attn);
    float* qkv  = (float*)p_qkv;
    float* attn = (float*)p_attn;

    const int flash_smem = FLASH_SMEM_FLOATS * (int)sizeof(float);  // ~118 KB
    cudaFuncSetAttribute(flash_attn_kernel,
                         cudaFuncAttributeMaxDynamicSharedMemorySize, flash_smem);

    // 1) fused QKV projection: [2048,4096] @ [4096,6144]
    {
        dim3 grid(QKV_N / 128, S_LEN / 128);
        sgemm128<<<grid, 256>>>(hidden, w_qkv, qkv, S_LEN, QKV_N, HID);
    }
    // 2) RoPE + head-major split
    rope_split_kernel<<<S_LEN, 256>>>(positions);
    // 3) causal GQA flash attention
    {
        dim3 grid(S_LEN / BR, NH);
        flash_attn_kernel<<<grid, 256, flash_smem>>>();
    }
    // 4) output projection: [2048,4096] @ [4096,4096]
    {
        dim3 grid(HID / 128, S_LEN / 128);
        sgemm128<<<grid, 256>>>(attn, w_o, out, S_LEN, HID, QS);
    }
}

// round 3
// speedup vs baseline: 2.0220x; 2.0220x over previous
#include <cuda_runtime.h>
#include <cuda_fp16.h>
#include <cstdint>
#include <math.h>

// ---------------- problem constants ----------------
#define S_LEN 2048
#define HID   4096
#define NH    32
#define NKV   8
#define HD    128
#define QS    (NH * HD)          // 4096
#define KVS   (NKV * HD)         // 1024
#define QKV_N (QS + 2 * KVS)     // 6144
#define SCALE 0.08838834764831845f  // 128^-0.5

// ---------------- scratch (static device globals; no allocs) ----------------
__device__ float g_qkv[S_LEN * QKV_N];       // QKV projection output [S, 6144]
__device__ float g_q[NH * S_LEN * HD];       // RoPE'd Q, head-major [h][s][d]
__device__ float g_k[NKV * S_LEN * HD];      // RoPE'd K, head-major
__device__ float g_v[NKV * S_LEN * HD];      // V, head-major
__device__ float g_attn[S_LEN * QS];         // attention output [s][h*128+d]

// fp16 split operands for tensor-core GEMMs
__device__ __half g_ah[S_LEN * HID];         // activation hi  [M,K]
__device__ __half g_al[S_LEN * HID];         // activation lo
__device__ __half g_wqh[QKV_N * HID];        // w_qkv^T hi [N,K]
__device__ __half g_wql[QKV_N * HID];        // w_qkv^T lo
__device__ __half g_woh[HID * QS];           // w_o^T hi   [N,K]
__device__ __half g_wol[HID * QS];           // w_o^T lo

// ==========================================================================
// small PTX helpers
// ==========================================================================
__device__ __forceinline__ uint32_t smem_to_u32(const void* p) {
    uint32_t a;
    asm("{ .reg .u64 t; cvta.to.shared.u64 t, %1; cvt.u32.u64 %0, t; }"
        : "=r"(a) : "l"(p));
    return a;
}
__device__ __forceinline__ void cp_async16(uint32_t dst, const void* src) {
    asm volatile("cp.async.cg.shared.global [%0], [%1], 16;"
                 :: "r"(dst), "l"(src) : "memory");
}
#define CP_COMMIT() asm volatile("cp.async.commit_group;" ::: "memory")
#define CP_WAIT(n)  asm volatile("cp.async.wait_group %0;" :: "n"(n) : "memory")

__device__ __forceinline__ void ldsm_x4(uint32_t* r, uint32_t addr) {
    asm volatile("ldmatrix.sync.aligned.m8n8.x4.shared.b16 {%0,%1,%2,%3}, [%4];"
                 : "=r"(r[0]), "=r"(r[1]), "=r"(r[2]), "=r"(r[3]) : "r"(addr));
}
__device__ __forceinline__ void ldsm_x2(uint32_t* r, uint32_t addr) {
    asm volatile("ldmatrix.sync.aligned.m8n8.x2.shared.b16 {%0,%1}, [%2];"
                 : "=r"(r[0]), "=r"(r[1]) : "r"(addr));
}
__device__ __forceinline__ void mma16816(float* c, const uint32_t* a, const uint32_t* b) {
    asm volatile("mma.sync.aligned.m16n8k16.row.col.f32.f16.f16.f32 "
                 "{%0,%1,%2,%3}, {%4,%5,%6,%7}, {%8,%9}, {%0,%1,%2,%3};"
                 : "+f"(c[0]), "+f"(c[1]), "+f"(c[2]), "+f"(c[3])
                 : "r"(a[0]), "r"(a[1]), "r"(a[2]), "r"(a[3]),
                   "r"(b[0]), "r"(b[1]));
}

// ==========================================================================
// split-fp16 HMMA GEMM: C[M,N] = (Ah+Al)[M,K] @ (Bh+Bl)[N,K]^T
// CTA tile 128x128, BK=32, 256 threads (8 warps, 2x4), warp tile 64x32.
// Tiles in smem: 128 rows x 32 fp16, row stride 80B (conflict-free ldmatrix).
// cp.async double buffer.
// ==========================================================================
#define ROW_B   80                    // padded row stride bytes (32 fp16 = 64B + 16)
#define TILE_B  (128 * ROW_B)         // 10240
#define STAGE_B (4 * TILE_B)          // 40960 (Ah, Al, Bh, Bl)
#define GEMM_SMEM (2 * STAGE_B)       // 81920

__global__ __launch_bounds__(256) void gemm_hmma_split(
    const __half* __restrict__ Ah, const __half* __restrict__ Al,
    const __half* __restrict__ Bh, const __half* __restrict__ Bl,
    float* __restrict__ C, int Nglob, int Kglob)
{
    extern __shared__ __align__(128) char smem[];
    const uint32_t sbase = smem_to_u32(smem);
    const int tid  = threadIdx.x;
    const int wid  = tid >> 5;
    const int lane = tid & 31;
    const int brow = blockIdx.y * 128;
    const int bcol = blockIdx.x * 128;
    const int NC   = Kglob / 32;

    const int wm = (wid >> 2) * 64;      // warp row offset within CTA tile
    const int wn = (wid & 3) * 32;       // warp col offset

    const __half* __restrict__ srcs[4] = { Ah, Al, Bh, Bl };

    // accumulators: 4 m-tiles x 4 n-tiles x 4 floats
    float acc[4][4][4];
#pragma unroll
    for (int i = 0; i < 4; i++)
#pragma unroll
        for (int j = 0; j < 4; j++)
#pragma unroll
            for (int e = 0; e < 4; e++) acc[i][j][e] = 0.0f;

    // ------- stage loader: 4 tiles x 512 x 16B chunks, 2048 chunks / 256 thr = 8 each
    auto load_stage = [&](int s, int c) {
        const int k0 = c * 32;
        const uint32_t stage = sbase + s * STAGE_B;
#pragma unroll
        for (int m = 0; m < 4; m++) {
            const int rowbase = (m < 2) ? brow : bcol;
            const __half* src = srcs[m];
            // 512 chunks: thread handles 2 (tid and tid+256)
#pragma unroll
            for (int t = 0; t < 2; t++) {
                int e  = tid + t * 256;       // 0..511
                int r  = e >> 2;              // row 0..127
                int cc = e & 3;               // 16B chunk within row
                const void* g = src + (size_t)(rowbase + r) * Kglob + k0 + cc * 8;
                cp_async16(stage + m * TILE_B + r * ROW_B + cc * 16, g);
            }
        }
    };

    load_stage(0, 0);
    CP_COMMIT();

    for (int c = 0; c < NC; c++) {
        if (c + 1 < NC) { load_stage((c + 1) & 1, c + 1); CP_COMMIT(); CP_WAIT(1); }
        else            { CP_WAIT(0); }
        __syncthreads();

        const uint32_t st = sbase + (c & 1) * STAGE_B;
        const uint32_t a_base = st;                       // Ah
        const uint32_t b_base = st + 2 * TILE_B;          // Bh

        // per-lane ldmatrix addresses (row part)
        const int arow = wm + (lane & 15);                // + i*16
        const int acol16 = (lane >> 4) * 16;              // 16B k-half select
        const int brow8 = wn + (lane & 7);                // + j*8
        const int bcol16 = ((lane >> 3) & 1) * 16;

#pragma unroll
        for (int ks = 0; ks < 2; ks++) {                  // two k16 steps per BK=32
            const int koff = ks * 32;                     // 16 fp16 = 32B
            uint32_t ahf[4][4], alf[4][4], bhf[4][2], blf[4][2];
#pragma unroll
            for (int i = 0; i < 4; i++) {
                uint32_t addr = a_base + (arow + i * 16) * ROW_B + acol16 + koff;
                ldsm_x4(ahf[i], addr);
                ldsm_x4(alf[i], addr + TILE_B);
            }
#pragma unroll
            for (int j = 0; j < 4; j++) {
                uint32_t addr = b_base + (brow8 + j * 8) * ROW_B + bcol16 + koff;
                ldsm_x2(bhf[j], addr);
                ldsm_x2(blf[j], addr + TILE_B);
            }
#pragma unroll
            for (int i = 0; i < 4; i++)
#pragma unroll
                for (int j = 0; j < 4; j++) {
                    mma16816(acc[i][j], ahf[i], bhf[j]);
                    mma16816(acc[i][j], ahf[i], blf[j]);
                    mma16816(acc[i][j], alf[i], bhf[j]);
                }
        }
        __syncthreads();
    }

    // ------- epilogue: c0,c1 -> (row, col..col+1); c2,c3 -> (row+8, ...)
    const int erow = brow + wm + (lane >> 2);
    const int ecol = bcol + wn + (lane & 3) * 2;
#pragma unroll
    for (int i = 0; i < 4; i++) {
#pragma unroll
        for (int j = 0; j < 4; j++) {
            float* p0 = C + (size_t)(erow + i * 16) * Nglob + ecol + j * 8;
            float* p1 = C + (size_t)(erow + i * 16 + 8) * Nglob + ecol + j * 8;
            *(float2*)p0 = make_float2(acc[i][j][0], acc[i][j][1]);
            *(float2*)p1 = make_float2(acc[i][j][2], acc[i][j][3]);
        }
    }
}

// ==========================================================================
// fp32 -> fp16 hi/lo split (row-major, same layout)
// ==========================================================================
__global__ __launch_bounds__(256) void convert_split(
    const float* __restrict__ x, __half* __restrict__ hi,
    __half* __restrict__ lo, int n4)
{
    int i = blockIdx.x * 256 + threadIdx.x;
    if (i >= n4) return;
    float4 v = ((const float4*)x)[i];
    float vals[4] = {v.x, v.y, v.z, v.w};
    __half hs[4], ls[4];
#pragma unroll
    for (int j = 0; j < 4; j++) {
        __half h = __float2half_rn(vals[j]);
        hs[j] = h;
        ls[j] = __float2half_rn(vals[j] - __half2float(h));
    }
    *(uint2*)(hi + i * 4) = *(uint2*)hs;
    *(uint2*)(lo + i * 4) = *(uint2*)ls;
}

// ==========================================================================
// W[K,N] fp32 -> W^T[N,K] fp16 hi/lo (32x32 tiled transpose)
// ==========================================================================
__global__ __launch_bounds__(256) void transpose_split(
    const float* __restrict__ W, __half* __restrict__ th,
    __half* __restrict__ tl, int K, int N)
{
    __shared__ float t[32][33];
    const int bx = blockIdx.x * 32;   // N offset
    const int by = blockIdx.y * 32;   // K offset
    const int tx = threadIdx.x;       // 0..31
    const int ty = threadIdx.y;       // 0..7
#pragma unroll
    for (int i = 0; i < 32; i += 8)
        t[ty + i][tx] = W[(size_t)(by + ty + i) * N + bx + tx];
    __syncthreads();
#pragma unroll
    for (int i = 0; i < 32; i += 8) {
        float v = t[tx][ty + i];
        __half h = __float2half_rn(v);
        size_t o = (size_t)(bx + ty + i) * K + by + tx;
        th[o] = h;
        tl[o] = __float2half_rn(v - __half2float(h));
    }
}

// ==========================================================================
// RoPE + split: g_qkv[s] -> g_q / g_k (NeoX rope) / g_v (copy), head-major.
// ==========================================================================
__global__ __launch_bounds__(256) void rope_split_kernel(const int* __restrict__ positions)
{
    const int s   = blockIdx.x;
    const int tid = threadIdx.x;
    __shared__ float cs[64], sn[64];

    if (tid < 64) {
        float inv_freq = powf(10000.0f, -((float)(2 * tid)) / 128.0f);
        float ang = (float)positions[s] * inv_freq;
        cs[tid] = cosf(ang);
        sn[tid] = sinf(ang);
    }
    __syncthreads();

    const float* row = g_qkv + (size_t)s * QKV_N;

    for (int idx = tid; idx < NH * 64; idx += 256) {
        int h = idx >> 6, d = idx & 63;
        float x1 = row[h * HD + d];
        float x2 = row[h * HD + d + 64];
        float* q = g_q + ((size_t)h * S_LEN + s) * HD;
        q[d]      = x1 * cs[d] - x2 * sn[d];
        q[d + 64] = x2 * cs[d] + x1 * sn[d];
    }
    for (int idx = tid; idx < NKV * 64; idx += 256) {
        int h = idx >> 6, d = idx & 63;
        const float* kr = row + QS;
        float x1 = kr[h * HD + d];
        float x2 = kr[h * HD + d + 64];
        float* k = g_k + ((size_t)h * S_LEN + s) * HD;
        k[d]      = x1 * cs[d] - x2 * sn[d];
        k[d + 64] = x2 * cs[d] + x1 * sn[d];
    }
    for (int idx = tid; idx < NKV * HD; idx += 256) {
        int h = idx >> 7, d = idx & 127;
        g_v[((size_t)h * S_LEN + s) * HD + d] = row[QS + KVS + h * HD + d];
    }
}

// ==========================================================================
// Flash attention, fp32, causal. Br=Bc=64, 256 threads.
// ==========================================================================
#define BR 64
#define BC 64
#define QK_STRIDE (BR + 4)
#define V_STRIDE  (HD + 4)
#define FLASH_SMEM_FLOATS (HD * QK_STRIDE + HD * QK_STRIDE \
                         + BC * V_STRIDE + BR * QK_STRIDE)

__global__ __launch_bounds__(256) void flash_attn_kernel()
{
    extern __shared__ float fsmem[];
    float* Qst = fsmem;
    float* Kst = Qst + HD * QK_STRIDE;
    float* Vs  = Kst + HD * QK_STRIDE;
    float* Ps  = Vs  + BC * V_STRIDE;

    const int qt  = blockIdx.x;
    const int h   = blockIdx.y;
    const int kvh = h >> 2;
    const int tid = threadIdx.x;
    const int ty  = tid >> 4;
    const int tx  = tid & 15;
    const int qbase = qt * BR;

    {
        const float* Qg = g_q + ((size_t)h * S_LEN + qbase) * HD;
        int r = tid & 63;
        int d0 = (tid >> 6) << 2;
#pragma unroll
        for (int i = 0; i < 8; i++) {
            int d = d0 + i * 16;
            float4 v = *(const float4*)(Qg + r * HD + d);
            Qst[(d + 0) * QK_STRIDE + r] = v.x;
            Qst[(d + 1) * QK_STRIDE + r] = v.y;
            Qst[(d + 2) * QK_STRIDE + r] = v.z;
            Qst[(d + 3) * QK_STRIDE + r] = v.w;
        }
    }

    float Ofrag[4][8];
    float m_i[4], l_i[4];
#pragma unroll
    for (int i = 0; i < 4; i++) {
        m_i[i] = -1e30f;
        l_i[i] = 0.0f;
#pragma unroll
        for (int j = 0; j < 8; j++) Ofrag[i][j] = 0.0f;
    }

    for (int jt = 0; jt <= qt; jt++) {
        const int kbase = jt * BC;
        {
            const float* Kg = g_k + ((size_t)kvh * S_LEN + kbase) * HD;
            const float* Vg = g_v + ((size_t)kvh * S_LEN + kbase) * HD;
            int c = tid & 63;
            int d0 = (tid >> 6) << 2;
#pragma unroll
            for (int i = 0; i < 8; i++) {
                int d = d0 + i * 16;
                float4 kv = *(const float4*)(Kg + c * HD + d);
                Kst[(d + 0) * QK_STRIDE + c] = kv.x;
                Kst[(d + 1) * QK_STRIDE + c] = kv.y;
                Kst[(d + 2) * QK_STRIDE + c] = kv.z;
                Kst[(d + 3) * QK_STRIDE + c] = kv.w;
                float4 vv = *(const float4*)(Vg + c * HD + d);
                *(float4*)&Vs[c * V_STRIDE + d] = vv;
            }
        }
        __syncthreads();

        float sfrag[4][4];
#pragma unroll
        for (int i = 0; i < 4; i++)
#pragma unroll
            for (int j = 0; j < 4; j++) sfrag[i][j] = 0.0f;

#pragma unroll 4
        for (int kk = 0; kk < HD; kk++) {
            float4 a = *(float4*)&Qst[kk * QK_STRIDE + ty * 4];
            float4 b = *(float4*)&Kst[kk * QK_STRIDE + tx * 4];
            float ar[4] = {a.x, a.y, a.z, a.w};
            float br[4] = {b.x, b.y, b.z, b.w};
#pragma unroll
            for (int i = 0; i < 4; i++)
#pragma unroll
                for (int j = 0; j < 4; j++)
                    sfrag[i][j] = fmaf(ar[i], br[j], sfrag[i][j]);
        }

        if (jt == qt) {
#pragma unroll
            for (int i = 0; i < 4; i++)
#pragma unroll
                for (int j = 0; j < 4; j++) {
                    float sv = sfrag[i][j] * SCALE;
                    sfrag[i][j] = (tx * 4 + j > ty * 4 + i) ? -1e30f : sv;
                }
        } else {
#pragma unroll
            for (int i = 0; i < 4; i++)
#pragma unroll
                for (int j = 0; j < 4; j++) sfrag[i][j] *= SCALE;
        }

#pragma unroll
        for (int i = 0; i < 4; i++) {
            float mloc = fmaxf(fmaxf(sfrag[i][0], sfrag[i][1]),
                               fmaxf(sfrag[i][2], sfrag[i][3]));
#pragma unroll
            for (int off = 8; off > 0; off >>= 1)
                mloc = fmaxf(mloc, __shfl_xor_sync(0xffffffffu, mloc, off, 16));

            float mnew  = fmaxf(m_i[i], mloc);
            float alpha = __expf(m_i[i] - mnew);
            float rsum = 0.0f;
            float p[4];
#pragma unroll
            for (int j = 0; j < 4; j++) {
                p[j] = __expf(sfrag[i][j] - mnew);
                rsum += p[j];
            }
            *(float4*)&Ps[(ty * 4 + i) * QK_STRIDE + tx * 4] =
                make_float4(p[0], p[1], p[2], p[3]);
#pragma unroll
            for (int off = 8; off > 0; off >>= 1)
                rsum += __shfl_xor_sync(0xffffffffu, rsum, off, 16);

            l_i[i] = l_i[i] * alpha + rsum;
            m_i[i] = mnew;
#pragma unroll
            for (int j = 0; j < 8; j++) Ofrag[i][j] *= alpha;
        }
        __syncthreads();

#pragma unroll 4
        for (int c = 0; c < BC; c++) {
            float4 v0 = *(float4*)&Vs[c * V_STRIDE + tx * 8];
            float4 v1 = *(float4*)&Vs[c * V_STRIDE + tx * 8 + 4];
            float vv[8] = {v0.x, v0.y, v0.z, v0.w, v1.x, v1.y, v1.z, v1.w};
#pragma unroll
            for (int i = 0; i < 4; i++) {
                float pv = Ps[(ty * 4 + i) * QK_STRIDE + c];
#pragma unroll
                for (int j = 0; j < 8; j++)
                    Ofrag[i][j] = fmaf(pv, vv[j], Ofrag[i][j]);
            }
        }
        __syncthreads();
    }

#pragma unroll
    for (int i = 0; i < 4; i++) {
        float inv_l = 1.0f / l_i[i];
        float* orow = g_attn + (size_t)(qbase + ty * 4 + i) * QS + h * HD + tx * 8;
        *(float4*)(orow) = make_float4(Ofrag[i][0] * inv_l, Ofrag[i][1] * inv_l,
                                       Ofrag[i][2] * inv_l, Ofrag[i][3] * inv_l);
        *(float4*)(orow + 4) = make_float4(Ofrag[i][4] * inv_l, Ofrag[i][5] * inv_l,
                                           Ofrag[i][6] * inv_l, Ofrag[i][7] * inv_l);
    }
}

// ==========================================================================
// launch
// ==========================================================================
extern "C" void kernel_launch(void* const* d_in, const int* in_sizes, int n_in,
                              void* d_out, int out_size)
{
    const int*   positions = (const int*)d_in[0];
    const float* hidden    = (const float*)d_in[1];
    const float* w_qkv     = (const float*)d_in[2];
    const float* w_o       = (const float*)d_in[3];
    float*       out       = (float*)d_out;

    void *p_qkv, *p_attn, *p_ah, *p_al, *p_wqh, *p_wql, *p_woh, *p_wol;
    cudaGetSymbolAddress(&p_qkv,  g_qkv);
    cudaGetSymbolAddress(&p_attn, g_attn);
    cudaGetSymbolAddress(&p_ah,   g_ah);
    cudaGetSymbolAddress(&p_al,   g_al);
    cudaGetSymbolAddress(&p_wqh,  g_wqh);
    cudaGetSymbolAddress(&p_wql,  g_wql);
    cudaGetSymbolAddress(&p_woh,  g_woh);
    cudaGetSymbolAddress(&p_wol,  g_wol);
    float* qkv  = (float*)p_qkv;
    float* attn = (float*)p_attn;
    __half* ah  = (__half*)p_ah;
    __half* al  = (__half*)p_al;
    __half* wqh = (__half*)p_wqh;
    __half* wql = (__half*)p_wql;
    __half* woh = (__half*)p_woh;
    __half* wol = (__half*)p_wol;

    const int flash_smem = FLASH_SMEM_FLOATS * (int)sizeof(float);
    cudaFuncSetAttribute(flash_attn_kernel,
                         cudaFuncAttributeMaxDynamicSharedMemorySize, flash_smem);
    cudaFuncSetAttribute(gemm_hmma_split,
                         cudaFuncAttributeMaxDynamicSharedMemorySize, GEMM_SMEM);

    // 1) operand prep for QKV GEMM
    {
        int n4 = (S_LEN * HID) / 4;
        convert_split<<<(n4 + 255) / 256, 256>>>(hidden, ah, al, n4);
        dim3 tg(QKV_N / 32, HID / 32);
        transpose_split<<<tg, dim3(32, 8)>>>(w_qkv, wqh, wql, HID, QKV_N);
    }
    // 2) QKV projection: [2048,4096] @ [4096,6144] via HMMA split-fp16
    {
        dim3 grid(QKV_N / 128, S_LEN / 128);
        gemm_hmma_split<<<grid, 256, GEMM_SMEM>>>(ah, al, wqh, wql, qkv, QKV_N, HID);
    }
    // 3) RoPE + head-major split
    rope_split_kernel<<<S_LEN, 256>>>(positions);
    // 4) causal GQA flash attention (fp32)
    {
        dim3 grid(S_LEN / BR, NH);
        flash_attn_kernel<<<grid, 256, flash_smem>>>();
    }
    // 5) operand prep for O GEMM
    {
        int n4 = (S_LEN * QS) / 4;
        convert_split<<<(n4 + 255) / 256, 256>>>(attn, ah, al, n4);
        dim3 tg(HID / 32, QS / 32);
        transpose_split<<<tg, dim3(32, 8)>>>(w_o, woh, wol, QS, HID);
    }
    // 6) output projection: [2048,4096] @ [4096,4096] via HMMA split-fp16
    {
        dim3 grid(HID / 128, S_LEN / 128);
        gemm_hmma_split<<<grid, 256, GEMM_SMEM>>>(ah, al, woh, wol, out, HID, QS);
    }
}